// round 1
// baseline (speedup 1.0000x reference)
#include <cuda_runtime.h>

// LSTM1: B=4096, T=2048, I=6, H=2. One thread per sequence; full recurrence
// in registers with packed f32x2 FMAs; tanh.approx.f32 activations; fused
// MLP head (relu -> 128 -> relu -> 1).

#define B_DIM 4096
#define T_DIM 2048
#define I_DIM 6

typedef unsigned long long ull;

__device__ __forceinline__ ull pack2(float lo, float hi) {
    ull r; asm("mov.b64 %0, {%1, %2};" : "=l"(r) : "f"(lo), "f"(hi)); return r;
}
__device__ __forceinline__ void unpack2(ull v, float& lo, float& hi) {
    asm("mov.b64 {%0, %1}, %2;" : "=f"(lo), "=f"(hi) : "l"(v));
}
__device__ __forceinline__ ull fma2(ull a, ull b, ull c) {
    ull d; asm("fma.rn.f32x2 %0, %1, %2, %3;" : "=l"(d) : "l"(a), "l"(b), "l"(c)); return d;
}
__device__ __forceinline__ ull mul2(ull a, ull b) {
    ull d; asm("mul.rn.f32x2 %0, %1, %2;" : "=l"(d) : "l"(a), "l"(b)); return d;
}
__device__ __forceinline__ float tanh_ap(float x) {
    float y; asm("tanh.approx.f32 %0, %1;" : "=f"(y) : "f"(x)); return y;
}

// sigmoid of both halves: 0.5*tanh(0.5*x) + 0.5
__device__ __forceinline__ ull sigm2(ull x, ull halfc) {
    ull xs = mul2(x, halfc);
    float a, b; unpack2(xs, a, b);
    a = tanh_ap(a); b = tanh_ap(b);
    return fma2(pack2(a, b), halfc, halfc);
}
__device__ __forceinline__ ull tanh2(ull x) {
    float a, b; unpack2(x, a, b);
    return pack2(tanh_ap(a), tanh_ap(b));
}

// One LSTM step. Gates stored as 4 f32x2 pairs: p=0 -> (i0,i1), p=1 -> (f0,f1),
// p=2 -> (g0,g1), p=3 -> (o0,o1) (PyTorch gate order i,f,g,o along 4H).
__device__ __forceinline__ void lstm_step(
    float x0, float x1, float x2, float x3, float x4, float x5,
    const ull (&wp)[4][6], const ull (&whp0)[4], const ull (&whp1)[4],
    const ull (&bp)[4], ull halfc,
    ull& cpack, float& h0, float& h1)
{
    ull xb[6];
    xb[0] = pack2(x0, x0); xb[1] = pack2(x1, x1); xb[2] = pack2(x2, x2);
    xb[3] = pack2(x3, x3); xb[4] = pack2(x4, x4); xb[5] = pack2(x5, x5);
    ull hb0 = pack2(h0, h0), hb1 = pack2(h1, h1);

    ull g0 = bp[0], g1 = bp[1], g2 = bp[2], g3 = bp[3];
#pragma unroll
    for (int i = 0; i < 6; i++) {
        g0 = fma2(xb[i], wp[0][i], g0);
        g1 = fma2(xb[i], wp[1][i], g1);
        g2 = fma2(xb[i], wp[2][i], g2);
        g3 = fma2(xb[i], wp[3][i], g3);
    }
    g0 = fma2(hb0, whp0[0], g0); g0 = fma2(hb1, whp1[0], g0);
    g1 = fma2(hb0, whp0[1], g1); g1 = fma2(hb1, whp1[1], g1);
    g2 = fma2(hb0, whp0[2], g2); g2 = fma2(hb1, whp1[2], g2);
    g3 = fma2(hb0, whp0[3], g3); g3 = fma2(hb1, whp1[3], g3);

    ull ig = sigm2(g0, halfc);
    ull fg = sigm2(g1, halfc);
    ull gg = tanh2(g2);
    ull og = sigm2(g3, halfc);

    cpack = fma2(fg, cpack, mul2(ig, gg));
    ull tc = tanh2(cpack);
    ull hp = mul2(og, tc);
    unpack2(hp, h0, h1);
}

__global__ void __launch_bounds__(32, 1) lstm_fused_kernel(
    const float* __restrict__ x,
    const float* __restrict__ w_ih, const float* __restrict__ w_hh,
    const float* __restrict__ b_ih, const float* __restrict__ b_hh,
    const float* __restrict__ fc1_w, const float* __restrict__ fc1_b,
    const float* __restrict__ fc_w, const float* __restrict__ fc_b,
    float* __restrict__ out)
{
    const int b = blockIdx.x * 32 + threadIdx.x;
    if (b >= B_DIM) return;

    // Pack weights into f32x2 pairs (broadcast loads, L1/L2-cached).
    ull wp[4][6], whp0[4], whp1[4], bp[4];
#pragma unroll
    for (int p = 0; p < 4; p++) {
#pragma unroll
        for (int i = 0; i < 6; i++)
            wp[p][i] = pack2(w_ih[(2 * p) * 6 + i], w_ih[(2 * p + 1) * 6 + i]);
        whp0[p] = pack2(w_hh[(2 * p) * 2 + 0], w_hh[(2 * p + 1) * 2 + 0]);
        whp1[p] = pack2(w_hh[(2 * p) * 2 + 1], w_hh[(2 * p + 1) * 2 + 1]);
        bp[p]   = pack2(b_ih[2 * p]     + b_hh[2 * p],
                        b_ih[2 * p + 1] + b_hh[2 * p + 1]);
    }
    const ull halfc = pack2(0.5f, 0.5f);

    const float4* xb4 = (const float4*)(x + (size_t)b * (T_DIM * I_DIM));
    float h0 = 0.f, h1 = 0.f;
    ull cpack = pack2(0.f, 0.f);

    // 4 steps per chunk = 24 floats = 6 float4 (16B-aligned: 96B chunks).
    float4 ca = xb4[0], cb = xb4[1], cc = xb4[2],
           cd = xb4[3], ce = xb4[4], cf = xb4[5];
    const int NCH = T_DIM / 4;  // 512

    for (int k = 0; k < NCH; k++) {
        // Double-buffer next chunk (last iter reloads itself; harmless).
        const int kn = (k + 1 < NCH) ? (k + 1) : k;
        const float4* nb = xb4 + 6 * kn;
        float4 na = nb[0], nb1 = nb[1], nc = nb[2],
               nd = nb[3], ne = nb[4], nf = nb[5];
        if (k + 16 < NCH)
            asm volatile("prefetch.global.L2 [%0];" :: "l"(xb4 + 6 * (k + 16)));

        lstm_step(ca.x, ca.y, ca.z, ca.w, cb.x, cb.y,
                  wp, whp0, whp1, bp, halfc, cpack, h0, h1);
        lstm_step(cb.z, cb.w, cc.x, cc.y, cc.z, cc.w,
                  wp, whp0, whp1, bp, halfc, cpack, h0, h1);
        lstm_step(cd.x, cd.y, cd.z, cd.w, ce.x, ce.y,
                  wp, whp0, whp1, bp, halfc, cpack, h0, h1);
        lstm_step(ce.z, ce.w, cf.x, cf.y, cf.z, cf.w,
                  wp, whp0, whp1, bp, halfc, cpack, h0, h1);

        ca = na; cb = nb1; cc = nc; cd = nd; ce = ne; cf = nf;
    }

    // Head: relu(h) -> fc1[128,2]+b, relu -> fc[1,128]+b
    const float r0 = fmaxf(h0, 0.f), r1 = fmaxf(h1, 0.f);
    float acc = fc_b[0];
#pragma unroll 8
    for (int j = 0; j < 128; j++) {
        const float2 w = ((const float2*)fc1_w)[j];
        float v = fmaf(w.x, r0, fmaf(w.y, r1, fc1_b[j]));
        v = fmaxf(v, 0.f);
        acc = fmaf(v, fc_w[j], acc);
    }
    out[b] = acc;
}

extern "C" void kernel_launch(void* const* d_in, const int* in_sizes, int n_in,
                              void* d_out, int out_size) {
    (void)in_sizes; (void)n_in; (void)out_size;
    lstm_fused_kernel<<<B_DIM / 32, 32>>>(
        (const float*)d_in[0],  // x
        (const float*)d_in[1],  // w_ih
        (const float*)d_in[2],  // w_hh
        (const float*)d_in[3],  // b_ih
        (const float*)d_in[4],  // b_hh
        (const float*)d_in[5],  // fc1_w
        (const float*)d_in[6],  // fc1_b
        (const float*)d_in[7],  // fc_w
        (const float*)d_in[8],  // fc_b
        (float*)d_out);
}